// round 11
// baseline (speedup 1.0000x reference)
#include <cuda_runtime.h>
#include <cuda_bf16.h>
#include <math.h>

#define N 8192
#define T2 128
#define NUM_CHUNKS 8
#define STRIDE 6144
#define TOTAL 51200
#define FADE 1228
#define GRID 148
#define BLK 512
#define GD 16
#define GC (GD * GD * GD)        // 4096
#define HCELL 0.003125f          // 0.05 / 16
#define INVH 320.0f

// -------- device scratch (no allocations allowed) --------
__device__ float g_S[NUM_CHUNKS][N * 3];          // smoothed chunks
__device__ float g_SM[N * 3];                     // sm output of current step
__device__ int g_mi[N];                           // per-query argmin index
__device__ int g_best[N];                         // scatter last-wins (monotone base)
__device__ int g_off[7][GC];                      // cell start offsets (exclusive scan)
__device__ int g_run[7][GC];                      // cell end offsets (after scatter)
__device__ int g_cell[7][N];                      // point indices sorted by cell
__device__ int g_ticket;                          // grid barrier (monotone forever)

// ---- ticket grid barrier: barrier k owns tickets [kG,(k+1)G); no reset ever ----
__device__ __forceinline__ void gsync() {
    __syncthreads();
    if (threadIdx.x == 0) {
        __threadfence();
        int t = atomicAdd(&g_ticket, 1);
        int target = (t / GRID + 1) * GRID;
        int cur;
        do {
            asm volatile("ld.acquire.gpu.global.b32 %0, [%1];"
                         : "=r"(cur) : "l"(&g_ticket));
        } while (cur < target);
    }
    __syncthreads();
}

__device__ __forceinline__ int cellco(float x) {
    int c = (int)(x * INVH);
    return min(GD - 1, max(0, c));
}

__global__ __launch_bounds__(BLK, 1) void k_persist(
    const float* __restrict__ chunks, float* __restrict__ out,
    const float* __restrict__ bw1, const float* __restrict__ bb1,
    const float* __restrict__ bw2, const float* __restrict__ bb2,
    const float* __restrict__ bw3, const float* __restrict__ bb3,
    const float* __restrict__ pw1, const float* __restrict__ pb1,
    const float* __restrict__ pw2, const float* __restrict__ pb2,
    const float* __restrict__ pw3, const float* __restrict__ pb3) {

    __shared__ union {
        int scan[BLK];
        struct { float fs[3][T2 + 12]; float h1[32][T2 + 12]; float h2[32][T2 + 12]; } cv;
    } sm;

    const int tid = threadIdx.x;
    const int gt = blockIdx.x * BLK + tid;
    const int GT = GRID * BLK;

    // ===== build: zero counts + reset best =====
    for (int j = gt; j < 7 * GC; j += GT) (&g_off[0][0])[j] = 0;
    for (int j = gt; j < N; j += GT) g_best[j] = -1;
    gsync();

    // count (grids for chunks 1..7; chunk data is immutable input)
    for (int idx = gt; idx < 7 * N; idx += GT) {
        int gi = idx >> 13, j = idx & (N - 1);
        const float* c = chunks + (size_t)(gi + 1) * N * 3 + (size_t)j * 3;
        int cell = (cellco(c[2]) * GD + cellco(c[1])) * GD + cellco(c[0]);
        atomicAdd(&g_off[gi][cell], 1);
    }
    gsync();

    // exclusive scan per grid (blocks 0..6, 8 cells per thread)
    if (blockIdx.x < 7) {
        int gi = blockIdx.x;
        int loc[8]; int s = 0;
#pragma unroll
        for (int t = 0; t < 8; t++) { loc[t] = g_off[gi][tid * 8 + t]; s += loc[t]; }
        sm.scan[tid] = s;
        __syncthreads();
        for (int d = 1; d < BLK; d <<= 1) {
            int v = (tid >= d) ? sm.scan[tid - d] : 0;
            __syncthreads();
            sm.scan[tid] += v;
            __syncthreads();
        }
        int run = (tid == 0) ? 0 : sm.scan[tid - 1];
#pragma unroll
        for (int t = 0; t < 8; t++) {
            g_off[gi][tid * 8 + t] = run;
            g_run[gi][tid * 8 + t] = run;
            run += loc[t];
        }
    }
    gsync();

    // scatter point indices into cell lists
    for (int idx = gt; idx < 7 * N; idx += GT) {
        int gi = idx >> 13, j = idx & (N - 1);
        const float* c = chunks + (size_t)(gi + 1) * N * 3 + (size_t)j * 3;
        int cell = (cellco(c[2]) * GD + cellco(c[1])) * GD + cellco(c[0]);
        int pos = atomicAdd(&g_run[gi][cell], 1);
        g_cell[gi][pos] = j;
    }
    gsync();

    for (int step = 1; step < NUM_CHUNKS; step++) {
        const float* C = chunks + (size_t)step * N * 3;
        const float* P = (step == 1) ? chunks : g_S[step - 1];
        int base = step * N;
        const int gi = step - 1;

        // ===== phase A: exact grid NN per query =====
        // d2 = fma(-2, dot, pp+cc); dot ascending FMA chain. MATH LOCKED.
        // lexicographic (value, index) min == first-occurrence argmin.
        for (int q = gt; q < N; q += GT) {
            float px = P[q * 3], py = P[q * 3 + 1], pz = P[q * 3 + 2];
            float pp = __fadd_rn(__fadd_rn(__fmul_rn(px, px), __fmul_rn(py, py)),
                                 __fmul_rn(pz, pz));
            int qx = cellco(px), qy = cellco(py), qz = cellco(pz);

            float best = __int_as_float(0x7f800000);
            int bestj = 0x7fffffff;

            for (int r = 0; r < GD; r++) {
                int x0 = max(qx - r, 0), x1 = min(qx + r, GD - 1);
                int y0 = max(qy - r, 0), y1 = min(qy + r, GD - 1);
                int z0 = max(qz - r, 0), z1 = min(qz + r, GD - 1);
                for (int zz = z0; zz <= z1; zz++)
                    for (int yy = y0; yy <= y1; yy++)
                        for (int xx = x0; xx <= x1; xx++) {
                            int cheb = max(abs(xx - qx), max(abs(yy - qy), abs(zz - qz)));
                            if (cheb != r) continue;
                            int cell = (zz * GD + yy) * GD + xx;
                            int s = g_off[gi][cell], e = g_run[gi][cell];
                            for (int t = s; t < e; t++) {
                                int j = g_cell[gi][t];
                                float cx = __ldg(&C[j * 3]);
                                float cy = __ldg(&C[j * 3 + 1]);
                                float cz = __ldg(&C[j * 3 + 2]);
                                float cc = __fadd_rn(__fadd_rn(__fmul_rn(cx, cx), __fmul_rn(cy, cy)),
                                                     __fmul_rn(cz, cz));
                                float d2 = __fmaf_rn(-2.0f,
                                    __fmaf_rn(pz, cz, __fmaf_rn(py, cy, __fmaf_rn(px, cx, 0.0f))),
                                    __fadd_rn(pp, cc));
                                if (d2 < best || (d2 == best && j < bestj)) { best = d2; bestj = j; }
                            }
                        }
                // unexamined rings >= r+1 lie at distance >= r*h; margin covers
                // fp error of computed d2 (~3e-9) and cell-assignment jitter.
                float rb = (float)r * HCELL;
                if (rb * rb > best + 1e-8f) break;
            }
            g_mi[q] = bestj;
        }
        gsync();

        // ============ phase B: scatter-atomic + MLP + 3 convs ==========
        for (int tile = blockIdx.x; tile < N / T2; tile += GRID) {
            int t0 = tile * T2;

            for (int l = tid; l < T2 + 12; l += BLK) {
                int g = t0 - 6 + l;
                float f0 = 0.f, f1 = 0.f, f2 = 0.f;
                if (g >= 0 && g < N) {
                    int mi = g_mi[g];
                    if (l >= 6 && l < T2 + 6)
                        atomicMax(&g_best[mi], base + g);   // last-wins winner

                    float x[6];
                    x[0] = P[g * 3];     x[1] = P[g * 3 + 1];  x[2] = P[g * 3 + 2];
                    x[3] = C[mi * 3];    x[4] = C[mi * 3 + 1]; x[5] = C[mi * 3 + 2];

                    float a[32];
#pragma unroll
                    for (int o = 0; o < 32; o++) {
                        float acc = pb1[o];
#pragma unroll
                        for (int q = 0; q < 6; q++) acc = fmaf(__ldg(&pw1[o * 6 + q]), x[q], acc);
                        a[o] = fmaxf(acc, 0.f);
                    }
                    float h[16];
#pragma unroll
                    for (int o = 0; o < 16; o++) {
                        float acc = pb2[o];
#pragma unroll
                        for (int q = 0; q < 32; q++) acc = fmaf(__ldg(&pw2[o * 32 + q]), a[q], acc);
                        h[o] = fmaxf(acc, 0.f);
                    }
                    float z = pb3[0];
#pragma unroll
                    for (int q = 0; q < 16; q++) z = fmaf(__ldg(&pw3[q]), h[q], z);
                    float w = 1.f / (1.f + expf(-z));

                    f0 = w * x[0] + (1.f - w) * x[3];
                    f1 = w * x[1] + (1.f - w) * x[4];
                    f2 = w * x[2] + (1.f - w) * x[5];
                }
                sm.cv.fs[0][l] = f0; sm.cv.fs[1][l] = f1; sm.cv.fs[2][l] = f2;
            }
            __syncthreads();

            for (int idx = tid; idx < 32 * (T2 + 8); idx += BLK) {
                int co = idx / (T2 + 8);
                int l = idx % (T2 + 8) + 2;
                int g = t0 - 6 + l;
                float vo = 0.f;
                if (g >= 0 && g < N) {
                    float acc = bb1[co];
#pragma unroll
                    for (int ci = 0; ci < 3; ci++)
#pragma unroll
                        for (int k = 0; k < 5; k++)
                            acc = fmaf(__ldg(&bw1[(co * 3 + ci) * 5 + k]), sm.cv.fs[ci][l - 2 + k], acc);
                    vo = fmaxf(acc, 0.f);
                }
                sm.cv.h1[co][l] = vo;
            }
            __syncthreads();

            for (int idx = tid; idx < 32 * (T2 + 4); idx += BLK) {
                int co = idx / (T2 + 4);
                int l = idx % (T2 + 4) + 4;
                int g = t0 - 6 + l;
                float vo = 0.f;
                if (g >= 0 && g < N) {
                    float acc = bb2[co];
#pragma unroll
                    for (int ci = 0; ci < 32; ci++) {
                        const float* wp = &bw2[(co * 32 + ci) * 5];
                        const float* hp = &sm.cv.h1[ci][l - 2];
                        acc = fmaf(__ldg(&wp[0]), hp[0], acc);
                        acc = fmaf(__ldg(&wp[1]), hp[1], acc);
                        acc = fmaf(__ldg(&wp[2]), hp[2], acc);
                        acc = fmaf(__ldg(&wp[3]), hp[3], acc);
                        acc = fmaf(__ldg(&wp[4]), hp[4], acc);
                    }
                    vo = fmaxf(acc, 0.f);
                }
                sm.cv.h2[co][l] = vo;
            }
            __syncthreads();

            for (int idx = tid; idx < 3 * T2; idx += BLK) {
                int co = idx / T2;
                int l = idx % T2 + 6;
                int g = t0 - 6 + l;
                float acc = bb3[co];
#pragma unroll
                for (int ci = 0; ci < 32; ci++) {
                    const float* wp = &bw3[(co * 32 + ci) * 5];
                    const float* hp = &sm.cv.h2[ci][l - 2];
                    acc = fmaf(__ldg(&wp[0]), hp[0], acc);
                    acc = fmaf(__ldg(&wp[1]), hp[1], acc);
                    acc = fmaf(__ldg(&wp[2]), hp[2], acc);
                    acc = fmaf(__ldg(&wp[3]), hp[3], acc);
                    acc = fmaf(__ldg(&wp[4]), hp[4], acc);
                }
                g_SM[g * 3 + co] = acc;
            }
            __syncthreads();
        }
        gsync();

        // ==== phase C: gather S[step]; copy SM -> S[step-1] ====
        for (int j = gt; j < N; j += GT) {
            int v = g_best[j];
            float o0, o1, o2;
            if (v >= base) {
                int n = v - base;
                o0 = g_SM[n * 3]; o1 = g_SM[n * 3 + 1]; o2 = g_SM[n * 3 + 2];
            } else {
                o0 = C[j * 3]; o1 = C[j * 3 + 1]; o2 = C[j * 3 + 2];
            }
            g_S[step][j * 3] = o0; g_S[step][j * 3 + 1] = o1; g_S[step][j * 3 + 2] = o2;
        }
        {
            float* dst = g_S[step - 1];
            for (int t = gt; t < N * 3; t += GT)
                dst[t] = g_SM[t];
        }
        gsync();
    }

    // ============ merge: fade-weighted gather ============
    for (int t = gt; t < TOTAL; t += GT) {
        float a0 = 0.f, a1 = 0.f, a2 = 0.f, ws = 0.f;
#pragma unroll
        for (int k = 0; k < NUM_CHUNKS; k++) {
            int off = t - k * STRIDE;
            if (off >= 0 && off < N) {
                float w = 1.f;
                if (off < FADE)           w = 0.1f + (float)off * (0.9f / 1227.f);
                else if (off >= N - FADE) w = 1.0f - (float)(off - (N - FADE)) * (0.9f / 1227.f);
                a0 = fmaf(g_S[k][off * 3], w, a0);
                a1 = fmaf(g_S[k][off * 3 + 1], w, a1);
                a2 = fmaf(g_S[k][off * 3 + 2], w, a2);
                ws += w;
            }
        }
        float inv = 1.f / fmaxf(ws, 1e-8f);
        out[t * 3] = a0 * inv;
        out[t * 3 + 1] = a1 * inv;
        out[t * 3 + 2] = a2 * inv;
    }
}

extern "C" void kernel_launch(void* const* d_in, const int* in_sizes, int n_in,
                              void* d_out, int out_size) {
    const float* chunks = (const float*)d_in[0];
    const float* bw1 = (const float*)d_in[1];  const float* bb1 = (const float*)d_in[2];
    const float* bw2 = (const float*)d_in[3];  const float* bb2 = (const float*)d_in[4];
    const float* bw3 = (const float*)d_in[5];  const float* bb3 = (const float*)d_in[6];
    const float* pw1 = (const float*)d_in[7];  const float* pb1 = (const float*)d_in[8];
    const float* pw2 = (const float*)d_in[9];  const float* pb2 = (const float*)d_in[10];
    const float* pw3 = (const float*)d_in[11]; const float* pb3 = (const float*)d_in[12];

    k_persist<<<GRID, BLK>>>(chunks, (float*)d_out,
                             bw1, bb1, bw2, bb2, bw3, bb3,
                             pw1, pb1, pw2, pb2, pw3, pb3);
}

// round 12
// speedup vs baseline: 11.8344x; 11.8344x over previous
#include <cuda_runtime.h>
#include <cuda_bf16.h>
#include <math.h>

#define N 8192
#define T2 128
#define NUM_CHUNKS 8
#define STRIDE 6144
#define TOTAL 51200
#define FADE 1228
#define GRID 148
#define BLK 512
#define GD 16
#define GC (GD * GD * GD)        // 4096
#define HCELL 0.003125f          // 0.05 / 16
#define INVH 320.0f
#define SLACK 1e-6f              // cell-geometry jitter slack (>> ulp jitter)
#define MARGIN 1e-7f             // > worst-case Gram-form fp error (~3e-8)

// -------- device scratch (no allocations allowed) --------
__device__ float g_S[NUM_CHUNKS][N * 3];          // smoothed chunks
__device__ float g_SM[N * 3];                     // sm output of current step
__device__ int g_mi[N];                           // per-query argmin index
__device__ int g_best[N];                         // scatter last-wins (monotone base)
__device__ int g_off[7][GC];                      // cell start offsets
__device__ int g_run[7][GC];                      // cell end offsets
__device__ float4 g_pts[7][N];                    // {x,y,z,cc} sorted by cell
__device__ int g_idx[7][N];                       // original j, same order
__device__ int g_ticket;                          // grid barrier (monotone forever)

// ---- ticket grid barrier: barrier k owns tickets [kG,(k+1)G); no reset ever ----
__device__ __forceinline__ void gsync() {
    __syncthreads();
    if (threadIdx.x == 0) {
        __threadfence();
        int t = atomicAdd(&g_ticket, 1);
        int target = (t / GRID + 1) * GRID;
        int cur;
        do {
            asm volatile("ld.acquire.gpu.global.b32 %0, [%1];"
                         : "=r"(cur) : "l"(&g_ticket));
        } while (cur < target);
    }
    __syncthreads();
}

__device__ __forceinline__ int cellco(float x) {
    int c = (int)(x * INVH);
    return min(GD - 1, max(0, c));
}

__global__ __launch_bounds__(BLK, 1) void k_persist(
    const float* __restrict__ chunks, float* __restrict__ out,
    const float* __restrict__ bw1, const float* __restrict__ bb1,
    const float* __restrict__ bw2, const float* __restrict__ bb2,
    const float* __restrict__ bw3, const float* __restrict__ bb3,
    const float* __restrict__ pw1, const float* __restrict__ pb1,
    const float* __restrict__ pw2, const float* __restrict__ pb2,
    const float* __restrict__ pw3, const float* __restrict__ pb3) {

    __shared__ union {
        int scan[BLK];
        struct { float fs[3][T2 + 12]; float h1[32][T2 + 12]; float h2[32][T2 + 12]; } cv;
    } sm;

    const int tid = threadIdx.x;
    const int gt = blockIdx.x * BLK + tid;
    const int GT = GRID * BLK;

    // ===== build: zero counts + reset best =====
    for (int j = gt; j < 7 * GC; j += GT) (&g_off[0][0])[j] = 0;
    for (int j = gt; j < N; j += GT) g_best[j] = -1;
    gsync();

    // count (grids for chunks 1..7; chunk data is immutable input)
    for (int idx = gt; idx < 7 * N; idx += GT) {
        int gi = idx >> 13, j = idx & (N - 1);
        const float* c = chunks + (size_t)(gi + 1) * N * 3 + (size_t)j * 3;
        int cell = (cellco(c[2]) * GD + cellco(c[1])) * GD + cellco(c[0]);
        atomicAdd(&g_off[gi][cell], 1);
    }
    gsync();

    // exclusive scan per grid (blocks 0..6, 8 cells per thread)
    if (blockIdx.x < 7) {
        int gi = blockIdx.x;
        int loc[8]; int s = 0;
#pragma unroll
        for (int t = 0; t < 8; t++) { loc[t] = g_off[gi][tid * 8 + t]; s += loc[t]; }
        sm.scan[tid] = s;
        __syncthreads();
        for (int d = 1; d < BLK; d <<= 1) {
            int v = (tid >= d) ? sm.scan[tid - d] : 0;
            __syncthreads();
            sm.scan[tid] += v;
            __syncthreads();
        }
        int run = (tid == 0) ? 0 : sm.scan[tid - 1];
#pragma unroll
        for (int t = 0; t < 8; t++) {
            g_off[gi][tid * 8 + t] = run;
            g_run[gi][tid * 8 + t] = run;
            run += loc[t];
        }
    }
    gsync();

    // scatter: pack {x,y,z,cc} + index per slot (cc uses the LOCKED formula)
    for (int idx = gt; idx < 7 * N; idx += GT) {
        int gi = idx >> 13, j = idx & (N - 1);
        const float* c = chunks + (size_t)(gi + 1) * N * 3 + (size_t)j * 3;
        float cx = c[0], cy = c[1], cz = c[2];
        int cell = (cellco(cz) * GD + cellco(cy)) * GD + cellco(cx);
        int pos = atomicAdd(&g_run[gi][cell], 1);
        float cc = __fadd_rn(__fadd_rn(__fmul_rn(cx, cx), __fmul_rn(cy, cy)),
                             __fmul_rn(cz, cz));
        g_pts[gi][pos] = make_float4(cx, cy, cz, cc);
        g_idx[gi][pos] = j;
    }
    gsync();

    for (int step = 1; step < NUM_CHUNKS; step++) {
        const float* C = chunks + (size_t)step * N * 3;
        const float* P = (step == 1) ? chunks : g_S[step - 1];
        int base = step * N;
        const int gi = step - 1;

        // ===== phase A: exact grid NN, out-of-box-aware pruning =====
        // Candidate d2 = fma(-2, dot, pp+cc), dot ascending FMA chain: MATH LOCKED.
        // Ring stop: any cell at cheb >= r+1 from the CLAMPED query cell has
        //   min-dist^2 >= (r*h)^2 + d2out   (out-of-box components survive on
        //   every axis; the axis achieving cheb adds >= r*h). Slack covers jitter.
        // Per-cell: skip if exact point-to-AABB dist^2 > best + MARGIN.
        // Pruned points are strictly > final min => first-occurrence preserved.
        for (int q = gt; q < N; q += GT) {
            float px = P[q * 3], py = P[q * 3 + 1], pz = P[q * 3 + 2];
            float pp = __fadd_rn(__fadd_rn(__fmul_rn(px, px), __fmul_rn(py, py)),
                                 __fmul_rn(pz, pz));
            int qx = cellco(px), qy = cellco(py), qz = cellco(pz);
            float dox = fmaxf(fmaxf(-px, px - 0.05f) - SLACK, 0.f);
            float doy = fmaxf(fmaxf(-py, py - 0.05f) - SLACK, 0.f);
            float doz = fmaxf(fmaxf(-pz, pz - 0.05f) - SLACK, 0.f);
            float d2out = dox * dox + doy * doy + doz * doz;

            float best = __int_as_float(0x7f800000);
            int bestj = 0x7fffffff;

            for (int r = 0; r < GD; r++) {
                int x0 = max(qx - r, 0), x1 = min(qx + r, GD - 1);
                int y0 = max(qy - r, 0), y1 = min(qy + r, GD - 1);
                int z0 = max(qz - r, 0), z1 = min(qz + r, GD - 1);
                for (int zz = z0; zz <= z1; zz++) {
                    float lz = zz * HCELL;
                    float sz = fmaxf(fmaxf(lz - SLACK - pz, pz - lz - HCELL - SLACK), 0.f);
                    for (int yy = y0; yy <= y1; yy++) {
                        float ly = yy * HCELL;
                        float sy = fmaxf(fmaxf(ly - SLACK - py, py - ly - HCELL - SLACK), 0.f);
                        float syz = sy * sy + sz * sz;
                        for (int xx = x0; xx <= x1; xx++) {
                            int cheb = max(abs(xx - qx), max(abs(yy - qy), abs(zz - qz)));
                            if (cheb != r) continue;
                            float lx = xx * HCELL;
                            float sx = fmaxf(fmaxf(lx - SLACK - px, px - lx - HCELL - SLACK), 0.f);
                            float d2min = sx * sx + syz;
                            if (d2min > best + MARGIN) continue;   // AABB prune
                            int cell = (zz * GD + yy) * GD + xx;
                            int s = g_off[gi][cell], e = g_run[gi][cell];
                            for (int t = s; t < e; t++) {
                                float4 c = g_pts[gi][t];
                                int j = g_idx[gi][t];
                                float d2 = __fmaf_rn(-2.0f,
                                    __fmaf_rn(pz, c.z, __fmaf_rn(py, c.y, __fmaf_rn(px, c.x, 0.0f))),
                                    __fadd_rn(pp, c.w));
                                if (d2 < best || (d2 == best && j < bestj)) { best = d2; bestj = j; }
                            }
                        }
                    }
                }
                float rb = fmaxf((float)r * HCELL - SLACK, 0.f);
                if (rb * rb + d2out > best + MARGIN) break;        // ring stop
            }
            g_mi[q] = bestj;
        }
        gsync();

        // ============ phase B: scatter-atomic + MLP + 3 convs ==========
        for (int tile = blockIdx.x; tile < N / T2; tile += GRID) {
            int t0 = tile * T2;

            for (int l = tid; l < T2 + 12; l += BLK) {
                int g = t0 - 6 + l;
                float f0 = 0.f, f1 = 0.f, f2 = 0.f;
                if (g >= 0 && g < N) {
                    int mi = g_mi[g];
                    if (l >= 6 && l < T2 + 6)
                        atomicMax(&g_best[mi], base + g);   // last-wins winner

                    float x[6];
                    x[0] = P[g * 3];     x[1] = P[g * 3 + 1];  x[2] = P[g * 3 + 2];
                    x[3] = C[mi * 3];    x[4] = C[mi * 3 + 1]; x[5] = C[mi * 3 + 2];

                    float a[32];
#pragma unroll
                    for (int o = 0; o < 32; o++) {
                        float acc = pb1[o];
#pragma unroll
                        for (int q = 0; q < 6; q++) acc = fmaf(__ldg(&pw1[o * 6 + q]), x[q], acc);
                        a[o] = fmaxf(acc, 0.f);
                    }
                    float h[16];
#pragma unroll
                    for (int o = 0; o < 16; o++) {
                        float acc = pb2[o];
#pragma unroll
                        for (int q = 0; q < 32; q++) acc = fmaf(__ldg(&pw2[o * 32 + q]), a[q], acc);
                        h[o] = fmaxf(acc, 0.f);
                    }
                    float z = pb3[0];
#pragma unroll
                    for (int q = 0; q < 16; q++) z = fmaf(__ldg(&pw3[q]), h[q], z);
                    float w = 1.f / (1.f + expf(-z));

                    f0 = w * x[0] + (1.f - w) * x[3];
                    f1 = w * x[1] + (1.f - w) * x[4];
                    f2 = w * x[2] + (1.f - w) * x[5];
                }
                sm.cv.fs[0][l] = f0; sm.cv.fs[1][l] = f1; sm.cv.fs[2][l] = f2;
            }
            __syncthreads();

            for (int idx = tid; idx < 32 * (T2 + 8); idx += BLK) {
                int co = idx / (T2 + 8);
                int l = idx % (T2 + 8) + 2;
                int g = t0 - 6 + l;
                float vo = 0.f;
                if (g >= 0 && g < N) {
                    float acc = bb1[co];
#pragma unroll
                    for (int ci = 0; ci < 3; ci++)
#pragma unroll
                        for (int k = 0; k < 5; k++)
                            acc = fmaf(__ldg(&bw1[(co * 3 + ci) * 5 + k]), sm.cv.fs[ci][l - 2 + k], acc);
                    vo = fmaxf(acc, 0.f);
                }
                sm.cv.h1[co][l] = vo;
            }
            __syncthreads();

            for (int idx = tid; idx < 32 * (T2 + 4); idx += BLK) {
                int co = idx / (T2 + 4);
                int l = idx % (T2 + 4) + 4;
                int g = t0 - 6 + l;
                float vo = 0.f;
                if (g >= 0 && g < N) {
                    float acc = bb2[co];
#pragma unroll
                    for (int ci = 0; ci < 32; ci++) {
                        const float* wp = &bw2[(co * 32 + ci) * 5];
                        const float* hp = &sm.cv.h1[ci][l - 2];
                        acc = fmaf(__ldg(&wp[0]), hp[0], acc);
                        acc = fmaf(__ldg(&wp[1]), hp[1], acc);
                        acc = fmaf(__ldg(&wp[2]), hp[2], acc);
                        acc = fmaf(__ldg(&wp[3]), hp[3], acc);
                        acc = fmaf(__ldg(&wp[4]), hp[4], acc);
                    }
                    vo = fmaxf(acc, 0.f);
                }
                sm.cv.h2[co][l] = vo;
            }
            __syncthreads();

            for (int idx = tid; idx < 3 * T2; idx += BLK) {
                int co = idx / T2;
                int l = idx % T2 + 6;
                int g = t0 - 6 + l;
                float acc = bb3[co];
#pragma unroll
                for (int ci = 0; ci < 32; ci++) {
                    const float* wp = &bw3[(co * 32 + ci) * 5];
                    const float* hp = &sm.cv.h2[ci][l - 2];
                    acc = fmaf(__ldg(&wp[0]), hp[0], acc);
                    acc = fmaf(__ldg(&wp[1]), hp[1], acc);
                    acc = fmaf(__ldg(&wp[2]), hp[2], acc);
                    acc = fmaf(__ldg(&wp[3]), hp[3], acc);
                    acc = fmaf(__ldg(&wp[4]), hp[4], acc);
                }
                g_SM[g * 3 + co] = acc;
            }
            __syncthreads();
        }
        gsync();

        // ==== phase C: gather S[step]; copy SM -> S[step-1] ====
        for (int j = gt; j < N; j += GT) {
            int v = g_best[j];
            float o0, o1, o2;
            if (v >= base) {
                int n = v - base;
                o0 = g_SM[n * 3]; o1 = g_SM[n * 3 + 1]; o2 = g_SM[n * 3 + 2];
            } else {
                o0 = C[j * 3]; o1 = C[j * 3 + 1]; o2 = C[j * 3 + 2];
            }
            g_S[step][j * 3] = o0; g_S[step][j * 3 + 1] = o1; g_S[step][j * 3 + 2] = o2;
        }
        {
            float* dst = g_S[step - 1];
            for (int t = gt; t < N * 3; t += GT)
                dst[t] = g_SM[t];
        }
        gsync();
    }

    // ============ merge: fade-weighted gather ============
    for (int t = gt; t < TOTAL; t += GT) {
        float a0 = 0.f, a1 = 0.f, a2 = 0.f, ws = 0.f;
#pragma unroll
        for (int k = 0; k < NUM_CHUNKS; k++) {
            int off = t - k * STRIDE;
            if (off >= 0 && off < N) {
                float w = 1.f;
                if (off < FADE)           w = 0.1f + (float)off * (0.9f / 1227.f);
                else if (off >= N - FADE) w = 1.0f - (float)(off - (N - FADE)) * (0.9f / 1227.f);
                a0 = fmaf(g_S[k][off * 3], w, a0);
                a1 = fmaf(g_S[k][off * 3 + 1], w, a1);
                a2 = fmaf(g_S[k][off * 3 + 2], w, a2);
                ws += w;
            }
        }
        float inv = 1.f / fmaxf(ws, 1e-8f);
        out[t * 3] = a0 * inv;
        out[t * 3 + 1] = a1 * inv;
        out[t * 3 + 2] = a2 * inv;
    }
}

extern "C" void kernel_launch(void* const* d_in, const int* in_sizes, int n_in,
                              void* d_out, int out_size) {
    const float* chunks = (const float*)d_in[0];
    const float* bw1 = (const float*)d_in[1];  const float* bb1 = (const float*)d_in[2];
    const float* bw2 = (const float*)d_in[3];  const float* bb2 = (const float*)d_in[4];
    const float* bw3 = (const float*)d_in[5];  const float* bb3 = (const float*)d_in[6];
    const float* pw1 = (const float*)d_in[7];  const float* pb1 = (const float*)d_in[8];
    const float* pw2 = (const float*)d_in[9];  const float* pb2 = (const float*)d_in[10];
    const float* pw3 = (const float*)d_in[11]; const float* pb3 = (const float*)d_in[12];

    k_persist<<<GRID, BLK>>>(chunks, (float*)d_out,
                             bw1, bb1, bw2, bb2, bw3, bb3,
                             pw1, pb1, pw2, pb2, pw3, pb3);
}

// round 15
// speedup vs baseline: 25.7155x; 2.1730x over previous
#include <cuda_runtime.h>
#include <cuda_bf16.h>
#include <math.h>

#define N 8192
#define T2 128
#define NUM_CHUNKS 8
#define STRIDE 6144
#define TOTAL 51200
#define FADE 1228
#define GRID 148
#define BLK 512
#define NWARP (BLK / 32)          // 16
#define GW (GRID * NWARP)         // 2368 warps
#define GD 16
#define GC (GD * GD * GD)         // 4096
#define HCELL 0.003125f           // 0.05 / 16
#define INVH 320.0f
#define SLACK 1e-6f               // cell-geometry jitter slack (>> ulp jitter)
#define MARGIN 1e-7f              // > worst-case Gram-form fp error (~3e-8)

// -------- device scratch (no allocations allowed) --------
__device__ float g_S[NUM_CHUNKS][N * 3];          // smoothed chunks
__device__ float g_SM[N * 3];                     // sm output of current step
__device__ int g_mi[N];                           // per-query argmin index
__device__ int g_best[N];                         // scatter last-wins (monotone base)
__device__ int g_off[7][GC];                      // cell start offsets
__device__ int g_run[7][GC];                      // cell end offsets
__device__ float4 g_pts[7][N];                    // {x,y,z,cc} sorted by cell
__device__ int g_idx[7][N];                       // original j, same order
__device__ int g_ticket;                          // grid barrier (monotone forever)

// ---- ticket grid barrier: barrier k owns tickets [kG,(k+1)G); no reset ever ----
__device__ __forceinline__ void gsync() {
    __syncthreads();
    if (threadIdx.x == 0) {
        __threadfence();
        int t = atomicAdd(&g_ticket, 1);
        int target = (t / GRID + 1) * GRID;
        int cur;
        do {
            asm volatile("ld.acquire.gpu.global.b32 %0, [%1];"
                         : "=r"(cur) : "l"(&g_ticket));
        } while (cur < target);
    }
    __syncthreads();
}

__device__ __forceinline__ int cellco(float x) {
    int c = (int)(x * INVH);
    return min(GD - 1, max(0, c));
}

__global__ __launch_bounds__(BLK, 1) void k_persist(
    const float* __restrict__ chunks, float* __restrict__ out,
    const float* __restrict__ bw1, const float* __restrict__ bb1,
    const float* __restrict__ bw2, const float* __restrict__ bb2,
    const float* __restrict__ bw3, const float* __restrict__ bb3,
    const float* __restrict__ pw1, const float* __restrict__ pb1,
    const float* __restrict__ pw2, const float* __restrict__ pb2,
    const float* __restrict__ pw3, const float* __restrict__ pb3) {

    __shared__ union {
        int scan[BLK];
        struct { float fs[3][T2 + 12]; float h1[32][T2 + 12]; float h2[32][T2 + 12]; } cv;
    } sm;

    const int tid = threadIdx.x;
    const int gt = blockIdx.x * BLK + tid;
    const int GT = GRID * BLK;
    const int lane = tid & 31;
    const int wid = blockIdx.x * NWARP + (tid >> 5);

    // ===== build: zero counts + reset best =====
    for (int j = gt; j < 7 * GC; j += GT) (&g_off[0][0])[j] = 0;
    for (int j = gt; j < N; j += GT) g_best[j] = -1;
    gsync();

    // count (grids for chunks 1..7; chunk data is immutable input)
    for (int idx = gt; idx < 7 * N; idx += GT) {
        int gi = idx >> 13, j = idx & (N - 1);
        const float* c = chunks + (size_t)(gi + 1) * N * 3 + (size_t)j * 3;
        int cell = (cellco(c[2]) * GD + cellco(c[1])) * GD + cellco(c[0]);
        atomicAdd(&g_off[gi][cell], 1);
    }
    gsync();

    // exclusive scan per grid (blocks 0..6, 8 cells per thread)
    if (blockIdx.x < 7) {
        int gi = blockIdx.x;
        int loc[8]; int s = 0;
#pragma unroll
        for (int t = 0; t < 8; t++) { loc[t] = g_off[gi][tid * 8 + t]; s += loc[t]; }
        sm.scan[tid] = s;
        __syncthreads();
        for (int d = 1; d < BLK; d <<= 1) {
            int v = (tid >= d) ? sm.scan[tid - d] : 0;
            __syncthreads();
            sm.scan[tid] += v;
            __syncthreads();
        }
        int run = (tid == 0) ? 0 : sm.scan[tid - 1];
#pragma unroll
        for (int t = 0; t < 8; t++) {
            g_off[gi][tid * 8 + t] = run;
            g_run[gi][tid * 8 + t] = run;
            run += loc[t];
        }
    }
    gsync();

    // scatter: pack {x,y,z,cc} + index per slot (cc uses the LOCKED formula)
    for (int idx = gt; idx < 7 * N; idx += GT) {
        int gi = idx >> 13, j = idx & (N - 1);
        const float* c = chunks + (size_t)(gi + 1) * N * 3 + (size_t)j * 3;
        float cx = c[0], cy = c[1], cz = c[2];
        int cell = (cellco(cz) * GD + cellco(cy)) * GD + cellco(cx);
        int pos = atomicAdd(&g_run[gi][cell], 1);
        float cc = __fadd_rn(__fadd_rn(__fmul_rn(cx, cx), __fmul_rn(cy, cy)),
                             __fmul_rn(cz, cz));
        g_pts[gi][pos] = make_float4(cx, cy, cz, cc);
        g_idx[gi][pos] = j;
    }
    gsync();

    for (int step = 1; step < NUM_CHUNKS; step++) {
        const float* C = chunks + (size_t)step * N * 3;
        const float* P = (step == 1) ? chunks : g_S[step - 1];
        int base = step * N;
        const int gi = step - 1;

        // ===== phase A: exact grid NN, WARP PER QUERY =====
        // Candidate d2 = fma(-2, dot, pp+cc), dot ascending FMA chain: MATH LOCKED.
        // Lanes stripe ring-r cells; AABB prune vs lane-local lbest (>= warp best
        // >= final best) is conservative; +inf init means "never prune before a
        // candidate exists" (R12 semantics). Warp u64-min == lexicographic (d2, j)
        // min == first-occurrence argmin. Ring stop identical to R12.
        for (int q = wid; q < N; q += GW) {
            float px = P[q * 3], py = P[q * 3 + 1], pz = P[q * 3 + 2];
            float pp = __fadd_rn(__fadd_rn(__fmul_rn(px, px), __fmul_rn(py, py)),
                                 __fmul_rn(pz, pz));
            int qx = cellco(px), qy = cellco(py), qz = cellco(pz);
            float dox = fmaxf(fmaxf(-px, px - 0.05f) - SLACK, 0.f);
            float doy = fmaxf(fmaxf(-py, py - 0.05f) - SLACK, 0.f);
            float doz = fmaxf(fmaxf(-pz, pz - 0.05f) - SLACK, 0.f);
            float d2out = dox * dox + doy * doy + doz * doz;

            unsigned long long bkey = 0xFFFFFFFFFFFFFFFFull;
            float lbest = __int_as_float(0x7f800000);      // +inf: never prunes early

            for (int r = 0; r < GD; r++) {
                int x0 = max(qx - r, 0), x1 = min(qx + r, GD - 1);
                int y0 = max(qy - r, 0), y1 = min(qy + r, GD - 1);
                int z0 = max(qz - r, 0), z1 = min(qz + r, GD - 1);
                int nx = x1 - x0 + 1, ny = y1 - y0 + 1, nz = z1 - z0 + 1;
                int nxy = nx * ny, total = nxy * nz;

                for (int idx = lane; idx < total; idx += 32) {
                    int zz = z0 + idx / nxy;
                    int rem = idx % nxy;
                    int yy = y0 + rem / nx;
                    int xx = x0 + rem % nx;
                    int cheb = max(abs(xx - qx), max(abs(yy - qy), abs(zz - qz)));
                    if (cheb != r) continue;
                    float lx = xx * HCELL, ly = yy * HCELL, lz = zz * HCELL;
                    float sx = fmaxf(fmaxf(lx - SLACK - px, px - lx - HCELL - SLACK), 0.f);
                    float sy = fmaxf(fmaxf(ly - SLACK - py, py - ly - HCELL - SLACK), 0.f);
                    float sz = fmaxf(fmaxf(lz - SLACK - pz, pz - lz - HCELL - SLACK), 0.f);
                    float d2min = sx * sx + sy * sy + sz * sz;
                    if (d2min > lbest + MARGIN) continue;   // AABB prune (R12 direction)
                    int cell = (zz * GD + yy) * GD + xx;
                    int s = g_off[gi][cell], e = g_run[gi][cell];
                    for (int t = s; t < e; t++) {
                        float4 c = g_pts[gi][t];
                        int j = g_idx[gi][t];
                        float d2 = __fmaf_rn(-2.0f,
                            __fmaf_rn(pz, c.z, __fmaf_rn(py, c.y, __fmaf_rn(px, c.x, 0.0f))),
                            __fadd_rn(pp, c.w));
                        unsigned int ob = __float_as_uint(d2);
                        ob = (ob & 0x80000000u) ? ~ob : (ob | 0x80000000u);
                        unsigned long long key =
                            ((unsigned long long)ob << 32) | (unsigned int)j;
                        if (key < bkey) { bkey = key; lbest = fminf(lbest, d2); }
                    }
                }
                // warp min-reduce (lexicographic (d2, j))
#pragma unroll
                for (int off = 16; off; off >>= 1) {
                    unsigned long long other = __shfl_xor_sync(0xffffffffu, bkey, off);
                    if (other < bkey) bkey = other;
                }
                unsigned int ob = (unsigned int)(bkey >> 32);
                float bestf = __uint_as_float((ob & 0x80000000u) ? (ob & 0x7fffffffu) : ~ob);
                lbest = fminf(lbest, bestf);               // fminf ignores NaN sentinel
                float rb = fmaxf((float)r * HCELL - SLACK, 0.f);
                if (rb * rb + d2out > bestf + MARGIN) break;  // ring stop (uniform;
                                                              // NaN sentinel -> false)
            }
            if (lane == 0) g_mi[q] = (int)(unsigned int)(bkey & 0xffffffffu);
        }
        gsync();

        // ============ phase B: scatter-atomic + MLP + 3 convs ==========
        for (int tile = blockIdx.x; tile < N / T2; tile += GRID) {
            int t0 = tile * T2;

            for (int l = tid; l < T2 + 12; l += BLK) {
                int g = t0 - 6 + l;
                float f0 = 0.f, f1 = 0.f, f2 = 0.f;
                if (g >= 0 && g < N) {
                    int mi = g_mi[g];
                    if (l >= 6 && l < T2 + 6)
                        atomicMax(&g_best[mi], base + g);   // last-wins winner

                    float x[6];
                    x[0] = P[g * 3];     x[1] = P[g * 3 + 1];  x[2] = P[g * 3 + 2];
                    x[3] = C[mi * 3];    x[4] = C[mi * 3 + 1]; x[5] = C[mi * 3 + 2];

                    float a[32];
#pragma unroll
                    for (int o = 0; o < 32; o++) {
                        float acc = pb1[o];
#pragma unroll
                        for (int q = 0; q < 6; q++) acc = fmaf(__ldg(&pw1[o * 6 + q]), x[q], acc);
                        a[o] = fmaxf(acc, 0.f);
                    }
                    float h[16];
#pragma unroll
                    for (int o = 0; o < 16; o++) {
                        float acc = pb2[o];
#pragma unroll
                        for (int q = 0; q < 32; q++) acc = fmaf(__ldg(&pw2[o * 32 + q]), a[q], acc);
                        h[o] = fmaxf(acc, 0.f);
                    }
                    float z = pb3[0];
#pragma unroll
                    for (int q = 0; q < 16; q++) z = fmaf(__ldg(&pw3[q]), h[q], z);
                    float w = 1.f / (1.f + expf(-z));

                    f0 = w * x[0] + (1.f - w) * x[3];
                    f1 = w * x[1] + (1.f - w) * x[4];
                    f2 = w * x[2] + (1.f - w) * x[5];
                }
                sm.cv.fs[0][l] = f0; sm.cv.fs[1][l] = f1; sm.cv.fs[2][l] = f2;
            }
            __syncthreads();

            for (int idx = tid; idx < 32 * (T2 + 8); idx += BLK) {
                int co = idx / (T2 + 8);
                int l = idx % (T2 + 8) + 2;
                int g = t0 - 6 + l;
                float vo = 0.f;
                if (g >= 0 && g < N) {
                    float acc = bb1[co];
#pragma unroll
                    for (int ci = 0; ci < 3; ci++)
#pragma unroll
                        for (int k = 0; k < 5; k++)
                            acc = fmaf(__ldg(&bw1[(co * 3 + ci) * 5 + k]), sm.cv.fs[ci][l - 2 + k], acc);
                    vo = fmaxf(acc, 0.f);
                }
                sm.cv.h1[co][l] = vo;
            }
            __syncthreads();

            for (int idx = tid; idx < 32 * (T2 + 4); idx += BLK) {
                int co = idx / (T2 + 4);
                int l = idx % (T2 + 4) + 4;
                int g = t0 - 6 + l;
                float vo = 0.f;
                if (g >= 0 && g < N) {
                    float acc = bb2[co];
#pragma unroll
                    for (int ci = 0; ci < 32; ci++) {
                        const float* wp = &bw2[(co * 32 + ci) * 5];
                        const float* hp = &sm.cv.h1[ci][l - 2];
                        acc = fmaf(__ldg(&wp[0]), hp[0], acc);
                        acc = fmaf(__ldg(&wp[1]), hp[1], acc);
                        acc = fmaf(__ldg(&wp[2]), hp[2], acc);
                        acc = fmaf(__ldg(&wp[3]), hp[3], acc);
                        acc = fmaf(__ldg(&wp[4]), hp[4], acc);
                    }
                    vo = fmaxf(acc, 0.f);
                }
                sm.cv.h2[co][l] = vo;
            }
            __syncthreads();

            for (int idx = tid; idx < 3 * T2; idx += BLK) {
                int co = idx / T2;
                int l = idx % T2 + 6;
                int g = t0 - 6 + l;
                float acc = bb3[co];
#pragma unroll
                for (int ci = 0; ci < 32; ci++) {
                    const float* wp = &bw3[(co * 32 + ci) * 5];
                    const float* hp = &sm.cv.h2[ci][l - 2];
                    acc = fmaf(__ldg(&wp[0]), hp[0], acc);
                    acc = fmaf(__ldg(&wp[1]), hp[1], acc);
                    acc = fmaf(__ldg(&wp[2]), hp[2], acc);
                    acc = fmaf(__ldg(&wp[3]), hp[3], acc);
                    acc = fmaf(__ldg(&wp[4]), hp[4], acc);
                }
                g_SM[g * 3 + co] = acc;
            }
            __syncthreads();
        }
        gsync();

        // ==== phase C: gather S[step]; copy SM -> S[step-1] ====
        for (int j = gt; j < N; j += GT) {
            int v = g_best[j];
            float o0, o1, o2;
            if (v >= base) {
                int n = v - base;
                o0 = g_SM[n * 3]; o1 = g_SM[n * 3 + 1]; o2 = g_SM[n * 3 + 2];
            } else {
                o0 = C[j * 3]; o1 = C[j * 3 + 1]; o2 = C[j * 3 + 2];
            }
            g_S[step][j * 3] = o0; g_S[step][j * 3 + 1] = o1; g_S[step][j * 3 + 2] = o2;
        }
        {
            float* dst = g_S[step - 1];
            for (int t = gt; t < N * 3; t += GT)
                dst[t] = g_SM[t];
        }
        gsync();
    }

    // ============ merge: fade-weighted gather ============
    for (int t = gt; t < TOTAL; t += GT) {
        float a0 = 0.f, a1 = 0.f, a2 = 0.f, ws = 0.f;
#pragma unroll
        for (int k = 0; k < NUM_CHUNKS; k++) {
            int off = t - k * STRIDE;
            if (off >= 0 && off < N) {
                float w = 1.f;
                if (off < FADE)           w = 0.1f + (float)off * (0.9f / 1227.f);
                else if (off >= N - FADE) w = 1.0f - (float)(off - (N - FADE)) * (0.9f / 1227.f);
                a0 = fmaf(g_S[k][off * 3], w, a0);
                a1 = fmaf(g_S[k][off * 3 + 1], w, a1);
                a2 = fmaf(g_S[k][off * 3 + 2], w, a2);
                ws += w;
            }
        }
        float inv = 1.f / fmaxf(ws, 1e-8f);
        out[t * 3] = a0 * inv;
        out[t * 3 + 1] = a1 * inv;
        out[t * 3 + 2] = a2 * inv;
    }
}

extern "C" void kernel_launch(void* const* d_in, const int* in_sizes, int n_in,
                              void* d_out, int out_size) {
    const float* chunks = (const float*)d_in[0];
    const float* bw1 = (const float*)d_in[1];  const float* bb1 = (const float*)d_in[2];
    const float* bw2 = (const float*)d_in[3];  const float* bb2 = (const float*)d_in[4];
    const float* bw3 = (const float*)d_in[5];  const float* bb3 = (const float*)d_in[6];
    const float* pw1 = (const float*)d_in[7];  const float* pb1 = (const float*)d_in[8];
    const float* pw2 = (const float*)d_in[9];  const float* pb2 = (const float*)d_in[10];
    const float* pw3 = (const float*)d_in[11]; const float* pb3 = (const float*)d_in[12];

    k_persist<<<GRID, BLK>>>(chunks, (float*)d_out,
                             bw1, bb1, bw2, bb2, bw3, bb3,
                             pw1, pb1, pw2, pb2, pw3, pb3);
}

// round 17
// speedup vs baseline: 33.7217x; 1.3113x over previous
#include <cuda_runtime.h>
#include <cuda_bf16.h>
#include <math.h>

#define N 8192
#define T2 128
#define NUM_CHUNKS 8
#define STRIDE 6144
#define TOTAL 51200
#define FADE 1228
#define GRID 148
#define BLK 512
#define NWARP (BLK / 32)          // 16
#define GW (GRID * NWARP)         // 2368 warps
#define GD 16
#define GC (GD * GD * GD)         // 4096
#define HCELL 0.003125f           // 0.05 / 16
#define INVH 320.0f
#define SLACK 1e-6f               // cell-geometry jitter slack (>> ulp jitter)
#define MARGIN 1e-7f              // > worst-case Gram-form fp error (~3e-8)

// -------- device scratch (no allocations allowed) --------
__device__ float g_S[NUM_CHUNKS][N * 3];          // smoothed chunks
__device__ float g_SM[N * 3];                     // sm output of current step
__device__ int g_mi[N];                           // per-query argmin index
__device__ int g_best[N];                         // scatter last-wins (monotone base)
__device__ int g_off[7][GC];                      // cell start offsets (contiguous lists)
__device__ int g_run[7][GC];                      // build-time fill cursor
__device__ float4 g_pts[7][N];                    // {x,y,z,cc} sorted by cell
__device__ int g_idx[7][N];                       // original j, same order
__device__ int g_ticket;                          // grid barrier (monotone forever)

// ---- ticket grid barrier: barrier k owns tickets [kG,(k+1)G); no reset ever ----
__device__ __forceinline__ void gsync() {
    __syncthreads();
    if (threadIdx.x == 0) {
        __threadfence();
        int t = atomicAdd(&g_ticket, 1);
        int target = (t / GRID + 1) * GRID;
        int cur;
        do {
            asm volatile("ld.acquire.gpu.global.b32 %0, [%1];"
                         : "=r"(cur) : "l"(&g_ticket));
        } while (cur < target);
    }
    __syncthreads();
}

__device__ __forceinline__ int cellco(float x) {
    int c = (int)(x * INVH);
    return min(GD - 1, max(0, c));
}

__global__ __launch_bounds__(BLK, 1) void k_persist(
    const float* __restrict__ chunks, float* __restrict__ out,
    const float* __restrict__ bw1, const float* __restrict__ bb1,
    const float* __restrict__ bw2, const float* __restrict__ bb2,
    const float* __restrict__ bw3, const float* __restrict__ bb3,
    const float* __restrict__ pw1, const float* __restrict__ pb1,
    const float* __restrict__ pw2, const float* __restrict__ pb2,
    const float* __restrict__ pw3, const float* __restrict__ pb3) {

    __shared__ union {
        int scan[BLK];
        int off[GC + 1];                           // phase A: cell offsets (16.4 KB)
        struct { float fs[3][T2 + 12]; float h1[32][T2 + 12]; float h2[32][T2 + 12]; } cv;
    } sm;

    const int tid = threadIdx.x;
    const int gt = blockIdx.x * BLK + tid;
    const int GT = GRID * BLK;
    const int lane = tid & 31;
    const int wid = blockIdx.x * NWARP + (tid >> 5);
    const float INF = __int_as_float(0x7f800000);

    // ===== build: zero counts + reset best =====
    for (int j = gt; j < 7 * GC; j += GT) (&g_off[0][0])[j] = 0;
    for (int j = gt; j < N; j += GT) g_best[j] = -1;
    gsync();

    // count (grids for chunks 1..7; chunk data is immutable input)
    for (int idx = gt; idx < 7 * N; idx += GT) {
        int gi = idx >> 13, j = idx & (N - 1);
        const float* c = chunks + (size_t)(gi + 1) * N * 3 + (size_t)j * 3;
        int cell = (cellco(c[2]) * GD + cellco(c[1])) * GD + cellco(c[0]);
        atomicAdd(&g_off[gi][cell], 1);
    }
    gsync();

    // exclusive scan per grid (blocks 0..6, 8 cells per thread)
    if (blockIdx.x < 7) {
        int gi = blockIdx.x;
        int loc[8]; int s = 0;
#pragma unroll
        for (int t = 0; t < 8; t++) { loc[t] = g_off[gi][tid * 8 + t]; s += loc[t]; }
        sm.scan[tid] = s;
        __syncthreads();
        for (int d = 1; d < BLK; d <<= 1) {
            int v = (tid >= d) ? sm.scan[tid - d] : 0;
            __syncthreads();
            sm.scan[tid] += v;
            __syncthreads();
        }
        int run = (tid == 0) ? 0 : sm.scan[tid - 1];
#pragma unroll
        for (int t = 0; t < 8; t++) {
            g_off[gi][tid * 8 + t] = run;
            g_run[gi][tid * 8 + t] = run;
            run += loc[t];
        }
    }
    gsync();

    // scatter: pack {x,y,z,cc} + index per slot (cc uses the LOCKED formula)
    for (int idx = gt; idx < 7 * N; idx += GT) {
        int gi = idx >> 13, j = idx & (N - 1);
        const float* c = chunks + (size_t)(gi + 1) * N * 3 + (size_t)j * 3;
        float cx = c[0], cy = c[1], cz = c[2];
        int cell = (cellco(cz) * GD + cellco(cy)) * GD + cellco(cx);
        int pos = atomicAdd(&g_run[gi][cell], 1);
        float cc = __fadd_rn(__fadd_rn(__fmul_rn(cx, cx), __fmul_rn(cy, cy)),
                             __fmul_rn(cz, cz));
        g_pts[gi][pos] = make_float4(cx, cy, cz, cc);
        g_idx[gi][pos] = j;
    }
    gsync();

    for (int step = 1; step < NUM_CHUNKS; step++) {
        const float* C = chunks + (size_t)step * N * 3;
        const float* P = (step == 1) ? chunks : g_S[step - 1];
        int base = step * N;
        const int gi = step - 1;

        // ===== phase A: exact grid NN, warp/query, two-pass bounded scan =====
        // Candidate d2 = fma(-2, dot, pp+cc), dot ascending FMA chain: MATH LOCKED.
        // Pass 1: cheb<=1 -> ub (warp-reduced). R = min r with
        // (r*h-SLACK)^2 + d2out > ub + MARGIN  (bench-validated ring-stop bound);
        // pass 2 scans cheb<=R once with AABB prune vs lbest (init ub, conservative).
        // Skipped cells strictly exceed best+MARGIN -> no tie lost; u64-min ==
        // lexicographic (d2, j) min == first-occurrence argmin.
        for (int i = tid; i <= GC; i += BLK)
            sm.off[i] = (i < GC) ? g_off[gi][i] : N;   // off[GC] = N (lists contiguous)
        __syncthreads();

        for (int q = wid; q < N; q += GW) {
            float px = P[q * 3], py = P[q * 3 + 1], pz = P[q * 3 + 2];
            float pp = __fadd_rn(__fadd_rn(__fmul_rn(px, px), __fmul_rn(py, py)),
                                 __fmul_rn(pz, pz));
            int qx = cellco(px), qy = cellco(py), qz = cellco(pz);
            float dox = fmaxf(fmaxf(-px, px - 0.05f) - SLACK, 0.f);
            float doy = fmaxf(fmaxf(-py, py - 0.05f) - SLACK, 0.f);
            float doz = fmaxf(fmaxf(-pz, pz - 0.05f) - SLACK, 0.f);
            float d2out = dox * dox + doy * doy + doz * doz;

            unsigned long long bkey = 0xFFFFFFFFFFFFFFFFull;

            // ---- pass 1: 27 cells at cheb<=1 (1 cell/lane; const-div indexing) ----
            if (lane < 27) {
                int zz = qz + lane / 9 - 1;
                int yy = qy + (lane / 3) % 3 - 1;
                int xx = qx + lane % 3 - 1;
                if (xx >= 0 && xx < GD && yy >= 0 && yy < GD && zz >= 0 && zz < GD) {
                    int cell = (zz * GD + yy) * GD + xx;
                    int s = sm.off[cell], e = sm.off[cell + 1];
                    for (int t = s; t < e; t++) {
                        float4 c = g_pts[gi][t];
                        int j = g_idx[gi][t];
                        float d2 = __fmaf_rn(-2.0f,
                            __fmaf_rn(pz, c.z, __fmaf_rn(py, c.y, __fmaf_rn(px, c.x, 0.0f))),
                            __fadd_rn(pp, c.w));
                        unsigned int ob = __float_as_uint(d2);
                        ob = (ob & 0x80000000u) ? ~ob : (ob | 0x80000000u);
                        unsigned long long key =
                            ((unsigned long long)ob << 32) | (unsigned int)j;
                        if (key < bkey) bkey = key;
                    }
                }
            }
#pragma unroll
            for (int off = 16; off; off >>= 1) {
                unsigned long long other = __shfl_xor_sync(0xffffffffu, bkey, off);
                if (other < bkey) bkey = other;
            }
            unsigned int ub32 = (unsigned int)(bkey >> 32);
            float ub = __uint_as_float((ub32 & 0x80000000u) ? (ub32 & 0x7fffffffu) : ~ub32);
            // (ub = NaN if no candidate yet -> R grows to GD: full pruned scan)

            // ---- radius bound (uniform scalar; NaN never breaks early) ----
            int R = 1;
            while (R < GD) {
                float rb = fmaxf((float)R * HCELL - SLACK, 0.f);
                if (rb * rb + d2out > ub + MARGIN) break;
                R++;
            }

            // ---- pass 2: one striped scan over cheb<=R, skipping cheb<=1 ----
            if (R > 1) {
                float lbest = fminf(ub, INF);              // NaN -> +inf (never prune)
                int x0 = max(qx - R, 0), x1 = min(qx + R, GD - 1);
                int y0 = max(qy - R, 0), y1 = min(qy + R, GD - 1);
                int z0 = max(qz - R, 0), z1 = min(qz + R, GD - 1);
                int nx = x1 - x0 + 1, ny = y1 - y0 + 1, nz = z1 - z0 + 1;
                int nxy = nx * ny, total = nxy * nz;

                for (int idx = lane; idx < total; idx += 32) {
                    int zz = z0 + idx / nxy;
                    int rem = idx - (zz - z0) * nxy;
                    int yy = y0 + rem / nx;
                    int xx = x0 + rem - (yy - y0) * nx;
                    int cheb = max(abs(xx - qx), max(abs(yy - qy), abs(zz - qz)));
                    if (cheb <= 1) continue;               // pass-1 territory
                    float lx = xx * HCELL, ly = yy * HCELL, lz = zz * HCELL;
                    float sx = fmaxf(fmaxf(lx - SLACK - px, px - lx - HCELL - SLACK), 0.f);
                    float sy = fmaxf(fmaxf(ly - SLACK - py, py - ly - HCELL - SLACK), 0.f);
                    float sz = fmaxf(fmaxf(lz - SLACK - pz, pz - lz - HCELL - SLACK), 0.f);
                    float d2min = sx * sx + sy * sy + sz * sz;
                    if (d2min > lbest + MARGIN) continue;  // AABB prune (conservative)
                    int cell = (zz * GD + yy) * GD + xx;
                    int s = sm.off[cell], e = sm.off[cell + 1];
                    for (int t = s; t < e; t++) {
                        float4 c = g_pts[gi][t];
                        int j = g_idx[gi][t];
                        float d2 = __fmaf_rn(-2.0f,
                            __fmaf_rn(pz, c.z, __fmaf_rn(py, c.y, __fmaf_rn(px, c.x, 0.0f))),
                            __fadd_rn(pp, c.w));
                        unsigned int ob = __float_as_uint(d2);
                        ob = (ob & 0x80000000u) ? ~ob : (ob | 0x80000000u);
                        unsigned long long key =
                            ((unsigned long long)ob << 32) | (unsigned int)j;
                        if (key < bkey) { bkey = key; lbest = fminf(lbest, d2); }
                    }
                }
#pragma unroll
                for (int off = 16; off; off >>= 1) {
                    unsigned long long other = __shfl_xor_sync(0xffffffffu, bkey, off);
                    if (other < bkey) bkey = other;
                }
            }
            if (lane == 0) g_mi[q] = (int)(unsigned int)(bkey & 0xffffffffu);
        }
        gsync();

        // ============ phase B: scatter-atomic + MLP + 3 convs ==========
        for (int tile = blockIdx.x; tile < N / T2; tile += GRID) {
            int t0 = tile * T2;

            for (int l = tid; l < T2 + 12; l += BLK) {
                int g = t0 - 6 + l;
                float f0 = 0.f, f1 = 0.f, f2 = 0.f;
                if (g >= 0 && g < N) {
                    int mi = g_mi[g];
                    if (l >= 6 && l < T2 + 6)
                        atomicMax(&g_best[mi], base + g);   // last-wins winner

                    float x[6];
                    x[0] = P[g * 3];     x[1] = P[g * 3 + 1];  x[2] = P[g * 3 + 2];
                    x[3] = C[mi * 3];    x[4] = C[mi * 3 + 1]; x[5] = C[mi * 3 + 2];

                    float a[32];
#pragma unroll
                    for (int o = 0; o < 32; o++) {
                        float acc = pb1[o];
#pragma unroll
                        for (int q2 = 0; q2 < 6; q2++) acc = fmaf(__ldg(&pw1[o * 6 + q2]), x[q2], acc);
                        a[o] = fmaxf(acc, 0.f);
                    }
                    float h[16];
#pragma unroll
                    for (int o = 0; o < 16; o++) {
                        float acc = pb2[o];
#pragma unroll
                        for (int q2 = 0; q2 < 32; q2++) acc = fmaf(__ldg(&pw2[o * 32 + q2]), a[q2], acc);
                        h[o] = fmaxf(acc, 0.f);
                    }
                    float z = pb3[0];
#pragma unroll
                    for (int q2 = 0; q2 < 16; q2++) z = fmaf(__ldg(&pw3[q2]), h[q2], z);
                    float w = 1.f / (1.f + expf(-z));

                    f0 = w * x[0] + (1.f - w) * x[3];
                    f1 = w * x[1] + (1.f - w) * x[4];
                    f2 = w * x[2] + (1.f - w) * x[5];
                }
                sm.cv.fs[0][l] = f0; sm.cv.fs[1][l] = f1; sm.cv.fs[2][l] = f2;
            }
            __syncthreads();

            for (int idx = tid; idx < 32 * (T2 + 8); idx += BLK) {
                int co = idx / (T2 + 8);
                int l = idx % (T2 + 8) + 2;
                int g = t0 - 6 + l;
                float vo = 0.f;
                if (g >= 0 && g < N) {
                    float acc = bb1[co];
#pragma unroll
                    for (int ci = 0; ci < 3; ci++)
#pragma unroll
                        for (int k = 0; k < 5; k++)
                            acc = fmaf(__ldg(&bw1[(co * 3 + ci) * 5 + k]), sm.cv.fs[ci][l - 2 + k], acc);
                    vo = fmaxf(acc, 0.f);
                }
                sm.cv.h1[co][l] = vo;
            }
            __syncthreads();

            for (int idx = tid; idx < 32 * (T2 + 4); idx += BLK) {
                int co = idx / (T2 + 4);
                int l = idx % (T2 + 4) + 4;
                int g = t0 - 6 + l;
                float vo = 0.f;
                if (g >= 0 && g < N) {
                    float acc = bb2[co];
#pragma unroll
                    for (int ci = 0; ci < 32; ci++) {
                        const float* wp = &bw2[(co * 32 + ci) * 5];
                        const float* hp = &sm.cv.h1[ci][l - 2];
                        acc = fmaf(__ldg(&wp[0]), hp[0], acc);
                        acc = fmaf(__ldg(&wp[1]), hp[1], acc);
                        acc = fmaf(__ldg(&wp[2]), hp[2], acc);
                        acc = fmaf(__ldg(&wp[3]), hp[3], acc);
                        acc = fmaf(__ldg(&wp[4]), hp[4], acc);
                    }
                    vo = fmaxf(acc, 0.f);
                }
                sm.cv.h2[co][l] = vo;
            }
            __syncthreads();

            for (int idx = tid; idx < 3 * T2; idx += BLK) {
                int co = idx / T2;
                int l = idx % T2 + 6;
                int g = t0 - 6 + l;
                float acc = bb3[co];
#pragma unroll
                for (int ci = 0; ci < 32; ci++) {
                    const float* wp = &bw3[(co * 32 + ci) * 5];
                    const float* hp = &sm.cv.h2[ci][l - 2];
                    acc = fmaf(__ldg(&wp[0]), hp[0], acc);
                    acc = fmaf(__ldg(&wp[1]), hp[1], acc);
                    acc = fmaf(__ldg(&wp[2]), hp[2], acc);
                    acc = fmaf(__ldg(&wp[3]), hp[3], acc);
                    acc = fmaf(__ldg(&wp[4]), hp[4], acc);
                }
                g_SM[g * 3 + co] = acc;
            }
            __syncthreads();
        }
        gsync();

        // ==== phase C: gather S[step]; copy SM -> S[step-1] ====
        for (int j = gt; j < N; j += GT) {
            int v = g_best[j];
            float o0, o1, o2;
            if (v >= base) {
                int n = v - base;
                o0 = g_SM[n * 3]; o1 = g_SM[n * 3 + 1]; o2 = g_SM[n * 3 + 2];
            } else {
                o0 = C[j * 3]; o1 = C[j * 3 + 1]; o2 = C[j * 3 + 2];
            }
            g_S[step][j * 3] = o0; g_S[step][j * 3 + 1] = o1; g_S[step][j * 3 + 2] = o2;
        }
        {
            float* dst = g_S[step - 1];
            for (int t = gt; t < N * 3; t += GT)
                dst[t] = g_SM[t];
        }
        gsync();
    }

    // ============ merge: fade-weighted gather ============
    for (int t = gt; t < TOTAL; t += GT) {
        float a0 = 0.f, a1 = 0.f, a2 = 0.f, ws = 0.f;
#pragma unroll
        for (int k = 0; k < NUM_CHUNKS; k++) {
            int off = t - k * STRIDE;
            if (off >= 0 && off < N) {
                float w = 1.f;
                if (off < FADE)           w = 0.1f + (float)off * (0.9f / 1227.f);
                else if (off >= N - FADE) w = 1.0f - (float)(off - (N - FADE)) * (0.9f / 1227.f);
                a0 = fmaf(g_S[k][off * 3], w, a0);
                a1 = fmaf(g_S[k][off * 3 + 1], w, a1);
                a2 = fmaf(g_S[k][off * 3 + 2], w, a2);
                ws += w;
            }
        }
        float inv = 1.f / fmaxf(ws, 1e-8f);
        out[t * 3] = a0 * inv;
        out[t * 3 + 1] = a1 * inv;
        out[t * 3 + 2] = a2 * inv;
    }
}

extern "C" void kernel_launch(void* const* d_in, const int* in_sizes, int n_in,
                              void* d_out, int out_size) {
    const float* chunks = (const float*)d_in[0];
    const float* bw1 = (const float*)d_in[1];  const float* bb1 = (const float*)d_in[2];
    const float* bw2 = (const float*)d_in[3];  const float* bb2 = (const float*)d_in[4];
    const float* bw3 = (const float*)d_in[5];  const float* bb3 = (const float*)d_in[6];
    const float* pw1 = (const float*)d_in[7];  const float* pb1 = (const float*)d_in[8];
    const float* pw2 = (const float*)d_in[9];  const float* pb2 = (const float*)d_in[10];
    const float* pw3 = (const float*)d_in[11]; const float* pb3 = (const float*)d_in[12];

    k_persist<<<GRID, BLK>>>(chunks, (float*)d_out,
                             bw1, bb1, bw2, bb2, bw3, bb3,
                             pw1, pb1, pw2, pb2, pw3, pb3);
}